// round 5
// baseline (speedup 1.0000x reference)
#include <cuda_runtime.h>
#include <cuda_bf16.h>
#include <math.h>

#define H_DIM 768
#define T_TAGS 3
#define S_LEN 512
#define B_SZ 128
#define F4_PER_ROW (H_DIM / 4)      // 192
#define CHUNKS (H_DIM / 128)        // 6
#define RQ 4                        // rows per quad
#define QPW 4                       // quads per warp (exact: 512*8*4*4 = 65536 rows)
#define PRED_BLOCKS 512
#define CRF_BLOCKS 64               // 2 batches per CRF block
#define LN2F 0.6931471805599453f

__device__ float g_part[B_SZ];
__device__ unsigned int g_cnt[B_SZ];   // zero-initialized; self-resetting each run
__device__ unsigned int g_done;        // zero-initialized; self-resetting each run

union SmemU {
    struct {
        float4 ws[3 * F4_PER_ROW];  // 9 KB
        float  bs[3];
    } pred;
    struct {
        float feats[S_LEN * 3];     // 6 KB
        float mats[S_LEN * 9];      // 18 KB
        float buf[256 * 9];         // 9 KB
        float lsA[S_LEN];
        float lsB[256];
        float red[256];
        float tr[9], etr[9], st[3], sp[3];
        int   is64;
    } crf;
    float fin[B_SZ];
};

__device__ __forceinline__ unsigned int ld_acquire(const unsigned int* p) {
    unsigned int v;
    asm volatile("ld.acquire.gpu.u32 %0, [%1];" : "=r"(v) : "l"(p));
    return v;
}

// Fast log-sum-exp helpers
__device__ __forceinline__ float lse3(float x, float y, float z) {
    float m = fmaxf(x, fmaxf(y, z));
    return m + __logf(__expf(x - m) + __expf(y - m) + __expf(z - m));
}

// ---------------- pred block body: 8 warps x 4 quads x 4 rows = 128 rows ----------------
__device__ __forceinline__ void pred_body(
    SmemU& sm, const float* __restrict__ x, const float* __restrict__ W,
    const float* __restrict__ bias, float* __restrict__ out, int nrows)
{
    auto& P = sm.pred;
    int tid = threadIdx.x;
    for (int i = tid; i < 3 * F4_PER_ROW; i += 256)
        P.ws[i] = reinterpret_cast<const float4*>(W)[i];
    if (tid < 3) P.bs[tid] = bias[tid];
    __syncthreads();

    int lane = tid & 31;
    int gw   = blockIdx.x * 8 + (tid >> 5);

    #pragma unroll
    for (int q = 0; q < QPW; q++) {
        int row0 = gw * (QPW * RQ) + q * RQ;
        if (row0 >= nrows) break;
        const float4* xr = reinterpret_cast<const float4*>(x)
                           + (size_t)row0 * F4_PER_ROW + lane;

        float a[RQ][3];
        #pragma unroll
        for (int r = 0; r < RQ; r++) { a[r][0] = 0.f; a[r][1] = 0.f; a[r][2] = 0.f; }

        #pragma unroll
        for (int i = 0; i < CHUNKS; i++) {
            float4 xv[RQ];
            #pragma unroll
            for (int r = 0; r < RQ; r++)
                xv[r] = __ldcs(&xr[(size_t)r * F4_PER_ROW + i * 32]);
            float4 w0 = P.ws[i * 32 + lane];
            float4 w1 = P.ws[192 + i * 32 + lane];
            float4 w2 = P.ws[384 + i * 32 + lane];
            #pragma unroll
            for (int r = 0; r < RQ; r++) {
                float4 t = xv[r];
                a[r][0] = fmaf(t.x, w0.x, fmaf(t.y, w0.y, fmaf(t.z, w0.z, fmaf(t.w, w0.w, a[r][0]))));
                a[r][1] = fmaf(t.x, w1.x, fmaf(t.y, w1.y, fmaf(t.z, w1.z, fmaf(t.w, w1.w, a[r][1]))));
                a[r][2] = fmaf(t.x, w2.x, fmaf(t.y, w2.y, fmaf(t.z, w2.z, fmaf(t.w, w2.w, a[r][2]))));
            }
        }

        #pragma unroll
        for (int off = 16; off; off >>= 1) {
            #pragma unroll
            for (int r = 0; r < RQ; r++) {
                a[r][0] += __shfl_xor_sync(0xffffffffu, a[r][0], off);
                a[r][1] += __shfl_xor_sync(0xffffffffu, a[r][1], off);
                a[r][2] += __shfl_xor_sync(0xffffffffu, a[r][2], off);
            }
        }
        if (lane < RQ) {
            float* o = out + (size_t)(row0 + lane) * 3;
            o[0] = a[lane][0] + P.bs[0];
            o[1] = a[lane][1] + P.bs[1];
            o[2] = a[lane][2] + P.bs[2];
        }
    }
    __syncthreads();
    if (tid == 0) {
        __threadfence();                       // publish output rows
        atomicAdd(&g_cnt[blockIdx.x >> 2], 1); // batch = bid/4 (128 rows per block)
    }
}

// ---------------- CRF body for one batch ----------------
__device__ __forceinline__ void crf_body(
    SmemU& sm, int b, const float* __restrict__ pred, const void* __restrict__ yraw,
    const float* __restrict__ trans, const float* __restrict__ start_t,
    const float* __restrict__ stop_t)
{
    auto& C = sm.crf;
    int tid = threadIdx.x;

    if (tid < 9) { float t = trans[tid]; C.tr[tid] = t; C.etr[tid] = __expf(t); }
    if (tid < 3) { C.st[tid] = start_t[tid]; C.sp[tid] = stop_t[tid]; }

    // y dtype sniff (values 0..2; LE int64 -> odd words zero; FP prob ~3^-16)
    if (tid == 0) {
        const int* y32p = (const int*)yraw;
        int is64 = 1;
        #pragma unroll
        for (int k = 0; k < 16; k++)
            if (y32p[2 * k + 1] != 0) { is64 = 0; break; }
        C.is64 = is64;
    }

    const float* pb = pred + (size_t)b * S_LEN * 3;
    for (int i = tid; i < S_LEN * 3; i += 256) C.feats[i] = __ldcg(&pb[i]);
    __syncthreads();

    const int is64 = C.is64;
    const long long* y64 = (const long long*)yraw + (size_t)b * S_LEN;
    const int*       y32 = (const int*)yraw       + (size_t)b * S_LEN;
    #define TAG(s) (is64 ? (int)y64[(s)] : y32[(s)])

    // gold path score
    float acc = 0.f;
    for (int s = tid; s < S_LEN; s += 256) {
        int tg = TAG(s);
        acc += C.feats[s * 3 + tg];
        if (s > 0) { int tp = TAG(s - 1); acc += C.tr[tp * 3 + tg]; }
    }
    if (tid == 0) acc += C.st[TAG(0)] + C.sp[TAG(S_LEN - 1)];
    C.red[tid] = acc;
    __syncthreads();
    for (int h = 128; h; h >>= 1) {
        if (tid < h) C.red[tid] += C.red[tid + h];
        __syncthreads();
    }
    float seq_score = C.red[0];

    // linear-domain leaves: exp(M_t) = exp(trans) (x) exp(feats_t), rank-1 separable
    for (int t = tid; t < S_LEN; t += 256) {
        float f0, f1, f2;
        if (t == 0) { f0 = C.feats[0] + C.st[0]; f1 = C.feats[1] + C.st[1]; f2 = C.feats[2] + C.st[2]; }
        else        { f0 = C.feats[t*3]; f1 = C.feats[t*3+1]; f2 = C.feats[t*3+2]; }
        float c = fmaxf(f0, fmaxf(f1, f2));
        float e0 = __expf(f0 - c), e1 = __expf(f1 - c), e2 = __expf(f2 - c);
        float* m = C.mats + t * 9;
        if (t == 0) {
            m[0]=e0; m[1]=e1; m[2]=e2; m[3]=e0; m[4]=e1; m[5]=e2; m[6]=e0; m[7]=e1; m[8]=e2;
        } else {
            m[0]=C.etr[0]*e0; m[1]=C.etr[1]*e1; m[2]=C.etr[2]*e2;
            m[3]=C.etr[3]*e0; m[4]=C.etr[4]*e1; m[5]=C.etr[5]*e2;
            m[6]=C.etr[6]*e0; m[7]=C.etr[7]*e1; m[8]=C.etr[8]*e2;
        }
        C.lsA[t] = c;
    }
    __syncthreads();

    // tree: numeric 3x3 matmuls + exact pow2 renorm (no MUFU)
    float* src = C.mats; float* dst = C.buf;
    float* lss = C.lsA;  float* lsd = C.lsB;
    int n = S_LEN;
    while (n > 1) {
        int half = n >> 1;
        if (tid < half) {
            const float* A  = src + (size_t)(2 * tid) * 9;
            const float* Bm = src + (size_t)(2 * tid + 1) * 9;
            float c[9];
            #pragma unroll
            for (int i2 = 0; i2 < 3; i2++)
                #pragma unroll
                for (int j = 0; j < 3; j++)
                    c[i2 * 3 + j] = fmaf(A[i2*3+0], Bm[0*3+j],
                                    fmaf(A[i2*3+1], Bm[1*3+j],
                                         A[i2*3+2] * Bm[2*3+j]));
            float m = c[0];
            #pragma unroll
            for (int e = 1; e < 9; e++) m = fmaxf(m, c[e]);
            int ebits = (__float_as_int(m) >> 23) - 127;
            float s = __int_as_float((127 - ebits) << 23);
            #pragma unroll
            for (int e = 0; e < 9; e++) dst[tid * 9 + e] = c[e] * s;
            lsd[tid] = lss[2 * tid] + lss[2 * tid + 1] + (float)ebits * LN2F;
        }
        __syncthreads();
        float* tmp = src; src = dst; dst = tmp;
        float* tl = lss; lss = lsd; lsd = tl;
        n = half;
    }

    if (tid == 0) {
        float z = src[0] * __expf(C.sp[0]) + src[1] * __expf(C.sp[1]) + src[2] * __expf(C.sp[2]);
        float logz = lss[0] + __logf(z);
        g_part[b] = seq_score - logz;
    }
    #undef TAG
}

// ---------------- fused kernel: 512 pred blocks + 64 CRF blocks, one wave ----------------
__global__ __launch_bounds__(256, 4) void fused_kernel(
    const float* __restrict__ x, const void* __restrict__ yraw,
    const float* __restrict__ W, const float* __restrict__ bias,
    const float* __restrict__ trans, const float* __restrict__ start_t,
    const float* __restrict__ stop_t, float* __restrict__ out,
    int nrows, int out_size)
{
    __shared__ SmemU sm;
    __shared__ int s_last;
    int tid = threadIdx.x;

    if (blockIdx.x < PRED_BLOCKS) {
        pred_body(sm, x, W, bias, out, nrows);
        return;
    }

    int c = blockIdx.x - PRED_BLOCKS;
    #pragma unroll
    for (int sub = 0; sub < 2; sub++) {
        int b = c * 2 + sub;
        if (tid == 0) {
            while (ld_acquire(&g_cnt[b]) < 4) __nanosleep(64);
        }
        __syncthreads();                 // acquire by tid0 + barrier orders the block
        crf_body(sm, b, out, yraw, trans, start_t, stop_t);
        __syncthreads();
        if (tid == 0) g_cnt[b] = 0;      // self-reset for next graph replay
    }

    // in-kernel finalize: last CRF block reduces the 128 partials
    if (tid == 0) {
        __threadfence();                 // publish g_part writes
        unsigned int o = atomicAdd(&g_done, 1);
        s_last = (o == CRF_BLOCKS - 1);
    }
    __syncthreads();
    if (s_last) {
        __threadfence();                 // acquire side
        if (tid < B_SZ) sm.fin[tid] = __ldcg(&g_part[tid]);
        __syncthreads();
        for (int h = B_SZ / 2; h; h >>= 1) {
            if (tid < h) sm.fin[tid] += sm.fin[tid + h];
            __syncthreads();
        }
        if (tid == 0) {
            out[out_size - 1] = -sm.fin[0] / (float)B_SZ;
            g_done = 0;                  // self-reset for next graph replay
        }
    }
}

// ---------------- launch ----------------
extern "C" void kernel_launch(void* const* d_in, const int* in_sizes, int n_in,
                              void* d_out, int out_size)
{
    const float* x     = (const float*)d_in[0];
    const void*  y     = d_in[1];
    const float* W     = (const float*)d_in[2];
    const float* bias  = (const float*)d_in[3];
    const float* trans = (const float*)d_in[4];
    const float* st    = (const float*)d_in[5];
    const float* sp    = (const float*)d_in[6];
    float* out = (float*)d_out;

    int nrows = in_sizes[0] / H_DIM;    // 65536

    fused_kernel<<<PRED_BLOCKS + CRF_BLOCKS, 256>>>(
        x, y, W, bias, trans, st, sp, out, nrows, out_size);
}

// round 6
// speedup vs baseline: 1.1849x; 1.1849x over previous
#include <cuda_runtime.h>
#include <cuda_bf16.h>
#include <math.h>

#define H_DIM 768
#define T_TAGS 3
#define S_LEN 512
#define B_SZ 128
#define F4_PER_ROW (H_DIM / 4)      // 192
#define CHUNKS (H_DIM / 128)        // 6
#define RQ 4                        // rows per quad
#define QPW 4                       // quads per warp
#define PRED_THREADS 128            // 4 warps -> 8 blocks/SM -> 1216 slots
#define PRED_BLOCKS 1024            // 1024 x 4 x 16 = 65536 rows, single wave
#define LN2F 0.6931471805599453f

__device__ float g_part[B_SZ];
__device__ unsigned int g_done;     // zero-init; self-resets each run

// -------------------- kernel 1: prediction = inputs @ W^T + b --------------------
// 128-thread CTAs so 8 fit per SM: the whole 1024-block grid is one resident
// wave (1216 slots) -> no wave-quantization tail. Inner loop = R4's proven
// 4-rows-per-quad, W-amortized form (64 regs).
__global__ __launch_bounds__(PRED_THREADS, 8) void pred_kernel(
    const float* __restrict__ x, const float* __restrict__ W,
    const float* __restrict__ bias, float* __restrict__ out, int nrows)
{
    __shared__ float4 ws[3 * F4_PER_ROW];   // 9 KB
    __shared__ float bs[3];
    for (int i = threadIdx.x; i < 3 * F4_PER_ROW; i += PRED_THREADS)
        ws[i] = reinterpret_cast<const float4*>(W)[i];
    if (threadIdx.x < 3) bs[threadIdx.x] = bias[threadIdx.x];
    __syncthreads();

    int lane = threadIdx.x & 31;
    int gw   = blockIdx.x * (PRED_THREADS / 32) + (threadIdx.x >> 5);

    #pragma unroll
    for (int q = 0; q < QPW; q++) {
        int row0 = gw * (QPW * RQ) + q * RQ;
        if (row0 >= nrows) break;
        const float4* xr = reinterpret_cast<const float4*>(x)
                           + (size_t)row0 * F4_PER_ROW + lane;

        float a[RQ][3];
        #pragma unroll
        for (int r = 0; r < RQ; r++) { a[r][0] = 0.f; a[r][1] = 0.f; a[r][2] = 0.f; }

        #pragma unroll
        for (int i = 0; i < CHUNKS; i++) {
            float4 xv[RQ];
            #pragma unroll
            for (int r = 0; r < RQ; r++)
                xv[r] = __ldcs(&xr[(size_t)r * F4_PER_ROW + i * 32]);
            float4 w0 = ws[i * 32 + lane];
            float4 w1 = ws[192 + i * 32 + lane];
            float4 w2 = ws[384 + i * 32 + lane];
            #pragma unroll
            for (int r = 0; r < RQ; r++) {
                float4 t = xv[r];
                a[r][0] = fmaf(t.x, w0.x, fmaf(t.y, w0.y, fmaf(t.z, w0.z, fmaf(t.w, w0.w, a[r][0]))));
                a[r][1] = fmaf(t.x, w1.x, fmaf(t.y, w1.y, fmaf(t.z, w1.z, fmaf(t.w, w1.w, a[r][1]))));
                a[r][2] = fmaf(t.x, w2.x, fmaf(t.y, w2.y, fmaf(t.z, w2.z, fmaf(t.w, w2.w, a[r][2]))));
            }
        }

        #pragma unroll
        for (int off = 16; off; off >>= 1) {
            #pragma unroll
            for (int r = 0; r < RQ; r++) {
                a[r][0] += __shfl_xor_sync(0xffffffffu, a[r][0], off);
                a[r][1] += __shfl_xor_sync(0xffffffffu, a[r][1], off);
                a[r][2] += __shfl_xor_sync(0xffffffffu, a[r][2], off);
            }
        }
        if (lane < RQ) {
            float* o = out + (size_t)(row0 + lane) * 3;
            o[0] = a[lane][0] + bs[0];
            o[1] = a[lane][1] + bs[1];
            o[2] = a[lane][2] + bs[2];
        }
    }
}

// -------------------- kernel 2: CRF (one block per batch) + fused finalize --------------------
// Linear-domain tree: leaves exp(M_t) = exp(trans) (x) exp(feats_t) (rank-1,
// 3 EX2/leaf); tree products = plain 3x3 fp32 matmuls with exact pow2 renorm.
__global__ __launch_bounds__(256) void crf_kernel(
    const float* __restrict__ pred, const void* __restrict__ yraw,
    const float* __restrict__ trans, const float* __restrict__ start_t,
    const float* __restrict__ stop_t, float* __restrict__ loss_out)
{
    __shared__ float feats[S_LEN * 3];      // 6 KB
    __shared__ float mats[S_LEN * 9];       // 18 KB
    __shared__ float buf[256 * 9];          // 9 KB
    __shared__ float lsA[S_LEN];
    __shared__ float lsB[256];
    __shared__ float red[256];
    __shared__ float tr[9], etr[9], st[3], sp[3];
    __shared__ int is64_s, s_last;

    int b   = blockIdx.x;
    int tid = threadIdx.x;

    if (tid < 9) { float t = trans[tid]; tr[tid] = t; etr[tid] = __expf(t); }
    if (tid < 3) { st[tid] = start_t[tid]; sp[tid] = stop_t[tid]; }

    // y dtype sniff (values 0..2; LE int64 -> odd words zero; FP prob ~3^-16)
    if (tid == 0) {
        const int* y32p = (const int*)yraw;
        int is64 = 1;
        #pragma unroll
        for (int k = 0; k < 16; k++)
            if (y32p[2 * k + 1] != 0) { is64 = 0; break; }
        is64_s = is64;
    }

    const float* pb = pred + (size_t)b * S_LEN * 3;
    for (int i = tid; i < S_LEN * 3; i += 256) feats[i] = pb[i];
    __syncthreads();

    const int is64 = is64_s;
    const long long* y64 = (const long long*)yraw + (size_t)b * S_LEN;
    const int*       y32 = (const int*)yraw       + (size_t)b * S_LEN;
    #define TAG(s) (is64 ? (int)y64[(s)] : y32[(s)])

    // gold path score
    float acc = 0.f;
    for (int s = tid; s < S_LEN; s += 256) {
        int tg = TAG(s);
        acc += feats[s * 3 + tg];
        if (s > 0) { int tp = TAG(s - 1); acc += tr[tp * 3 + tg]; }
    }
    if (tid == 0) acc += st[TAG(0)] + sp[TAG(S_LEN - 1)];
    red[tid] = acc;
    __syncthreads();
    for (int h = 128; h; h >>= 1) {
        if (tid < h) red[tid] += red[tid + h];
        __syncthreads();
    }
    float seq_score = red[0];

    // linear-domain leaves
    for (int t = tid; t < S_LEN; t += 256) {
        float f0, f1, f2;
        if (t == 0) { f0 = feats[0] + st[0]; f1 = feats[1] + st[1]; f2 = feats[2] + st[2]; }
        else        { f0 = feats[t*3]; f1 = feats[t*3+1]; f2 = feats[t*3+2]; }
        float c = fmaxf(f0, fmaxf(f1, f2));
        float e0 = __expf(f0 - c), e1 = __expf(f1 - c), e2 = __expf(f2 - c);
        float* m = mats + t * 9;
        if (t == 0) {
            m[0]=e0; m[1]=e1; m[2]=e2; m[3]=e0; m[4]=e1; m[5]=e2; m[6]=e0; m[7]=e1; m[8]=e2;
        } else {
            m[0]=etr[0]*e0; m[1]=etr[1]*e1; m[2]=etr[2]*e2;
            m[3]=etr[3]*e0; m[4]=etr[4]*e1; m[5]=etr[5]*e2;
            m[6]=etr[6]*e0; m[7]=etr[7]*e1; m[8]=etr[8]*e2;
        }
        lsA[t] = c;
    }
    __syncthreads();

    // tree: numeric 3x3 matmuls + exact pow2 renorm (no MUFU)
    float* src = mats; float* dst = buf;
    float* lss = lsA;  float* lsd = lsB;
    int n = S_LEN;
    while (n > 1) {
        int half = n >> 1;
        if (tid < half) {
            const float* A  = src + (size_t)(2 * tid) * 9;
            const float* Bm = src + (size_t)(2 * tid + 1) * 9;
            float c[9];
            #pragma unroll
            for (int i2 = 0; i2 < 3; i2++)
                #pragma unroll
                for (int j = 0; j < 3; j++)
                    c[i2 * 3 + j] = fmaf(A[i2*3+0], Bm[0*3+j],
                                    fmaf(A[i2*3+1], Bm[1*3+j],
                                         A[i2*3+2] * Bm[2*3+j]));
            float m = c[0];
            #pragma unroll
            for (int e = 1; e < 9; e++) m = fmaxf(m, c[e]);
            int ebits = (__float_as_int(m) >> 23) - 127;
            float s = __int_as_float((127 - ebits) << 23);
            #pragma unroll
            for (int e = 0; e < 9; e++) dst[tid * 9 + e] = c[e] * s;
            lsd[tid] = lss[2 * tid] + lss[2 * tid + 1] + (float)ebits * LN2F;
        }
        __syncthreads();
        float* tmp = src; src = dst; dst = tmp;
        float* tl = lss; lss = lsd; lsd = tl;
        n = half;
    }

    if (tid == 0) {
        float z = src[0] * __expf(sp[0]) + src[1] * __expf(sp[1]) + src[2] * __expf(sp[2]);
        float logz = lss[0] + __logf(z);
        g_part[b] = seq_score - logz;
    }
    #undef TAG

    // ---- fused finalize: last block to arrive reduces all partials ----
    __syncthreads();
    if (tid == 0) {
        __threadfence();
        unsigned int o = atomicAdd(&g_done, 1);
        s_last = (o == B_SZ - 1);
    }
    __syncthreads();
    if (s_last) {
        __threadfence();
        if (tid < B_SZ) red[tid] = __ldcg(&g_part[tid]);
        __syncthreads();
        for (int h = B_SZ / 2; h; h >>= 1) {
            if (tid < h) red[tid] += red[tid + h];
            __syncthreads();
        }
        if (tid == 0) {
            *loss_out = -red[0] / (float)B_SZ;
            g_done = 0;                  // self-reset for next graph replay
        }
    }
}

// -------------------- launch --------------------
extern "C" void kernel_launch(void* const* d_in, const int* in_sizes, int n_in,
                              void* d_out, int out_size)
{
    const float* x     = (const float*)d_in[0];
    const void*  y     = d_in[1];
    const float* W     = (const float*)d_in[2];
    const float* bias  = (const float*)d_in[3];
    const float* trans = (const float*)d_in[4];
    const float* st    = (const float*)d_in[5];
    const float* sp    = (const float*)d_in[6];
    float* out = (float*)d_out;

    int nrows = in_sizes[0] / H_DIM;    // 65536

    pred_kernel<<<PRED_BLOCKS, PRED_THREADS>>>(x, W, bias, out, nrows);
    crf_kernel<<<B_SZ, 256>>>(out, y, trans, st, sp, out + (out_size - 1));
}

// round 7
// speedup vs baseline: 1.1916x; 1.0057x over previous
#include <cuda_runtime.h>
#include <cuda_bf16.h>
#include <math.h>

#define H_DIM 768
#define T_TAGS 3
#define S_LEN 512
#define B_SZ 128
#define F4_PER_ROW (H_DIM / 4)      // 192
#define CHUNKS (H_DIM / 128)        // 6
#define RQ 4
#define QPW 4
#define PRED_THREADS 128            // 4 warps -> 8 blocks/SM -> single wave
#define PRED_BLOCKS 1024
#define SEG 16                      // timesteps per lane in CRF warp
#define LN2F 0.6931471805599453f
#define FULLM 0xffffffffu

__device__ float g_part[B_SZ];
__device__ unsigned int g_done;     // zero-init; self-resets each run

// -------------------- kernel 1: prediction (unchanged from R6, proven) --------------------
__global__ __launch_bounds__(PRED_THREADS, 8) void pred_kernel(
    const float* __restrict__ x, const float* __restrict__ W,
    const float* __restrict__ bias, float* __restrict__ out, int nrows)
{
    __shared__ float4 ws[3 * F4_PER_ROW];
    __shared__ float bs[3];
    for (int i = threadIdx.x; i < 3 * F4_PER_ROW; i += PRED_THREADS)
        ws[i] = reinterpret_cast<const float4*>(W)[i];
    if (threadIdx.x < 3) bs[threadIdx.x] = bias[threadIdx.x];
    __syncthreads();

    int lane = threadIdx.x & 31;
    int gw   = blockIdx.x * (PRED_THREADS / 32) + (threadIdx.x >> 5);

    #pragma unroll
    for (int q = 0; q < QPW; q++) {
        int row0 = gw * (QPW * RQ) + q * RQ;
        if (row0 >= nrows) break;
        const float4* xr = reinterpret_cast<const float4*>(x)
                           + (size_t)row0 * F4_PER_ROW + lane;

        float a[RQ][3];
        #pragma unroll
        for (int r = 0; r < RQ; r++) { a[r][0] = 0.f; a[r][1] = 0.f; a[r][2] = 0.f; }

        #pragma unroll
        for (int i = 0; i < CHUNKS; i++) {
            float4 xv[RQ];
            #pragma unroll
            for (int r = 0; r < RQ; r++)
                xv[r] = __ldcs(&xr[(size_t)r * F4_PER_ROW + i * 32]);
            float4 w0 = ws[i * 32 + lane];
            float4 w1 = ws[192 + i * 32 + lane];
            float4 w2 = ws[384 + i * 32 + lane];
            #pragma unroll
            for (int r = 0; r < RQ; r++) {
                float4 t = xv[r];
                a[r][0] = fmaf(t.x, w0.x, fmaf(t.y, w0.y, fmaf(t.z, w0.z, fmaf(t.w, w0.w, a[r][0]))));
                a[r][1] = fmaf(t.x, w1.x, fmaf(t.y, w1.y, fmaf(t.z, w1.z, fmaf(t.w, w1.w, a[r][1]))));
                a[r][2] = fmaf(t.x, w2.x, fmaf(t.y, w2.y, fmaf(t.z, w2.z, fmaf(t.w, w2.w, a[r][2]))));
            }
        }

        #pragma unroll
        for (int off = 16; off; off >>= 1) {
            #pragma unroll
            for (int r = 0; r < RQ; r++) {
                a[r][0] += __shfl_xor_sync(FULLM, a[r][0], off);
                a[r][1] += __shfl_xor_sync(FULLM, a[r][1], off);
                a[r][2] += __shfl_xor_sync(FULLM, a[r][2], off);
            }
        }
        if (lane < RQ) {
            float* o = out + (size_t)(row0 + lane) * 3;
            o[0] = a[lane][0] + bs[0];
            o[1] = a[lane][1] + bs[1];
            o[2] = a[lane][2] + bs[2];
        }
    }
}

// -------------------- kernel 2: CRF, one WARP per batch, no block barriers --------------------
__device__ __forceinline__ void renorm9(float a[9], float& ls) {
    float m = a[0];
    #pragma unroll
    for (int e = 1; e < 9; e++) m = fmaxf(m, a[e]);
    int eb = (__float_as_int(m) >> 23) - 127;
    float s = __int_as_float((127 - eb) << 23);   // exact 2^-eb
    #pragma unroll
    for (int e = 0; e < 9; e++) a[e] *= s;
    ls += (float)eb * LN2F;
}

__global__ __launch_bounds__(32) void crf_kernel(
    const float* __restrict__ pred, const void* __restrict__ yraw,
    const float* __restrict__ trans, const float* __restrict__ start_t,
    const float* __restrict__ stop_t, float* __restrict__ loss_out)
{
    __shared__ float tr_s[9], st_s[3], sp_s[3];
    int b = blockIdx.x, lane = threadIdx.x;

    float tv = (lane < 9) ? trans[lane] : 0.f;
    if (lane < 9) tr_s[lane] = tv;
    if (lane < 3) { st_s[lane] = start_t[lane]; sp_s[lane] = stop_t[lane]; }
    float etr[9];
    #pragma unroll
    for (int j = 0; j < 9; j++) etr[j] = __expf(__shfl_sync(FULLM, tv, j));
    __syncwarp();

    // y dtype sniff (values 0..2; LE int64 -> odd 32-bit words zero)
    const int* yw = (const int*)yraw;
    int oddw = (lane < 16) ? yw[2 * lane + 1] : 0;
    int stride = (__ballot_sync(FULLM, oddw != 0) == 0u) ? 2 : 1;  // int64 -> read low words stride 2
    const int* yb = yw + (size_t)b * S_LEN * stride;

    int t0 = lane * SEG;

    // Load this lane's 16 timesteps of feats (48 floats, 16B-aligned)
    float f[3 * SEG];
    const float4* pf = reinterpret_cast<const float4*>(pred + (size_t)b * S_LEN * 3 + (size_t)t0 * 3);
    #pragma unroll
    for (int i = 0; i < 12; i++) {
        float4 v = pf[i];
        f[4*i] = v.x; f[4*i+1] = v.y; f[4*i+2] = v.z; f[4*i+3] = v.w;
    }

    // Tags for the segment (+ predecessor)
    int tg[SEG];
    #pragma unroll
    for (int k = 0; k < SEG; k++) tg[k] = yb[(t0 + k) * stride];
    int tprev = (lane > 0) ? yb[(t0 - 1) * stride] : 0;

    // ---- gold path partial ----
    float gold = 0.f;
    #pragma unroll
    for (int k = 0; k < SEG; k++) {
        int t = tg[k];
        gold += (t == 0) ? f[3*k] : ((t == 1) ? f[3*k+1] : f[3*k+2]);
        int tp = (k == 0) ? tprev : tg[k-1];
        if (t0 + k > 0) gold += tr_s[tp * 3 + t];
    }
    if (lane == 0)  gold += st_s[tg[0]];
    if (lane == 31) gold += sp_s[tg[SEG-1]];
    #pragma unroll
    for (int off = 16; off; off >>= 1) gold += __shfl_xor_sync(FULLM, gold, off);

    // ---- sequential chain of 16 leaf matrices (linear domain, pow2 renorm) ----
    float a[9], ls;
    {
        float f0 = f[0], f1 = f[1], f2 = f[2];
        if (lane == 0) { f0 += st_s[0]; f1 += st_s[1]; f2 += st_s[2]; }
        float c = fmaxf(f0, fmaxf(f1, f2));
        float e0 = __expf(f0 - c), e1 = __expf(f1 - c), e2 = __expf(f2 - c);
        ls = c;
        if (lane == 0) {           // rank-1 leaf (a0 vector broadcast to rows)
            a[0]=e0; a[1]=e1; a[2]=e2; a[3]=e0; a[4]=e1; a[5]=e2; a[6]=e0; a[7]=e1; a[8]=e2;
        } else {
            #pragma unroll
            for (int i = 0; i < 3; i++) {
                a[i*3+0] = etr[i*3+0] * e0;
                a[i*3+1] = etr[i*3+1] * e1;
                a[i*3+2] = etr[i*3+2] * e2;
            }
        }
    }
    #pragma unroll
    for (int k = 1; k < SEG; k++) {
        float f0 = f[3*k], f1 = f[3*k+1], f2 = f[3*k+2];
        float c = fmaxf(f0, fmaxf(f1, f2));
        float e0 = __expf(f0 - c), e1 = __expf(f1 - c), e2 = __expf(f2 - c);
        ls += c;
        float n[9];
        #pragma unroll
        for (int i = 0; i < 3; i++) {
            n[i*3+0] = fmaf(a[i*3], etr[0], fmaf(a[i*3+1], etr[3], a[i*3+2] * etr[6])) * e0;
            n[i*3+1] = fmaf(a[i*3], etr[1], fmaf(a[i*3+1], etr[4], a[i*3+2] * etr[7])) * e1;
            n[i*3+2] = fmaf(a[i*3], etr[2], fmaf(a[i*3+1], etr[5], a[i*3+2] * etr[8])) * e2;
        }
        #pragma unroll
        for (int e = 0; e < 9; e++) a[e] = n[e];
        if ((k & 3) == 3) renorm9(a, ls);
    }

    // ---- 5-level shuffle tree (order-preserving: lane i combines with i+off) ----
    #pragma unroll
    for (int off = 1; off < 32; off <<= 1) {
        float bm[9];
        #pragma unroll
        for (int e = 0; e < 9; e++) bm[e] = __shfl_down_sync(FULLM, a[e], off);
        float lsb = __shfl_down_sync(FULLM, ls, off);
        if ((lane & (2 * off - 1)) == 0) {
            float n[9];
            #pragma unroll
            for (int i = 0; i < 3; i++) {
                n[i*3+0] = fmaf(a[i*3], bm[0], fmaf(a[i*3+1], bm[3], a[i*3+2] * bm[6]));
                n[i*3+1] = fmaf(a[i*3], bm[1], fmaf(a[i*3+1], bm[4], a[i*3+2] * bm[7]));
                n[i*3+2] = fmaf(a[i*3], bm[2], fmaf(a[i*3+1], bm[5], a[i*3+2] * bm[8]));
            }
            #pragma unroll
            for (int e = 0; e < 9; e++) a[e] = n[e];
            ls += lsb;
            renorm9(a, ls);
        }
    }

    if (lane == 0) {
        float z = a[0] * __expf(sp_s[0]) + a[1] * __expf(sp_s[1]) + a[2] * __expf(sp_s[2]);
        g_part[b] = gold - (ls + __logf(z));
    }

    // ---- fused finalize: last warp reduces all 128 partials ----
    int done = 0;
    if (lane == 0) {
        __threadfence();
        done = (int)atomicAdd(&g_done, 1);
    }
    done = __shfl_sync(FULLM, done, 0);
    if (done == B_SZ - 1) {
        __threadfence();
        float s = __ldcg(&g_part[lane])      + __ldcg(&g_part[lane + 32])
                + __ldcg(&g_part[lane + 64]) + __ldcg(&g_part[lane + 96]);
        #pragma unroll
        for (int off = 16; off; off >>= 1) s += __shfl_xor_sync(FULLM, s, off);
        if (lane == 0) {
            *loss_out = -s / (float)B_SZ;
            g_done = 0;                      // self-reset for next graph replay
        }
    }
}

// -------------------- launch --------------------
extern "C" void kernel_launch(void* const* d_in, const int* in_sizes, int n_in,
                              void* d_out, int out_size)
{
    const float* x     = (const float*)d_in[0];
    const void*  y     = d_in[1];
    const float* W     = (const float*)d_in[2];
    const float* bias  = (const float*)d_in[3];
    const float* trans = (const float*)d_in[4];
    const float* st    = (const float*)d_in[5];
    const float* sp    = (const float*)d_in[6];
    float* out = (float*)d_out;

    int nrows = in_sizes[0] / H_DIM;    // 65536

    pred_kernel<<<PRED_BLOCKS, PRED_THREADS>>>(x, W, bias, out, nrows);
    crf_kernel<<<B_SZ, 32>>>(out, y, trans, st, sp, out + (out_size - 1));
}

// round 8
// speedup vs baseline: 1.2346x; 1.0360x over previous
#include <cuda_runtime.h>
#include <cuda_bf16.h>
#include <math.h>

#define H_DIM 768
#define T_TAGS 3
#define S_LEN 512
#define B_SZ 128
#define F4_PER_ROW (H_DIM / 4)      // 192
#define CHUNKS (H_DIM / 128)        // 6
#define RQ 4
#define QPW 4
#define PRED_THREADS 128            // 4 warps -> 8 blocks/SM -> single wave
#define PRED_BLOCKS 1024
#define SEG 8                       // timesteps per lane (64 lanes x 8 = 512)
#define LN2F 0.6931471805599453f
#define FULLM 0xffffffffu

__device__ float g_part[B_SZ];
__device__ unsigned int g_done;     // zero-init; self-resets each run

// -------------------- kernel 1: prediction (R6 form, proven ~32us) --------------------
__global__ __launch_bounds__(PRED_THREADS, 8) void pred_kernel(
    const float* __restrict__ x, const float* __restrict__ W,
    const float* __restrict__ bias, float* __restrict__ out, int nrows)
{
    __shared__ float4 ws[3 * F4_PER_ROW];
    __shared__ float bs[3];
    for (int i = threadIdx.x; i < 3 * F4_PER_ROW; i += PRED_THREADS)
        ws[i] = reinterpret_cast<const float4*>(W)[i];
    if (threadIdx.x < 3) bs[threadIdx.x] = bias[threadIdx.x];
    __syncthreads();

    int lane = threadIdx.x & 31;
    int gw   = blockIdx.x * (PRED_THREADS / 32) + (threadIdx.x >> 5);

    #pragma unroll
    for (int q = 0; q < QPW; q++) {
        int row0 = gw * (QPW * RQ) + q * RQ;
        if (row0 >= nrows) break;
        const float4* xr = reinterpret_cast<const float4*>(x)
                           + (size_t)row0 * F4_PER_ROW + lane;

        float a[RQ][3];
        #pragma unroll
        for (int r = 0; r < RQ; r++) { a[r][0] = 0.f; a[r][1] = 0.f; a[r][2] = 0.f; }

        #pragma unroll
        for (int i = 0; i < CHUNKS; i++) {
            float4 xv[RQ];
            #pragma unroll
            for (int r = 0; r < RQ; r++)
                xv[r] = __ldcs(&xr[(size_t)r * F4_PER_ROW + i * 32]);
            float4 w0 = ws[i * 32 + lane];
            float4 w1 = ws[192 + i * 32 + lane];
            float4 w2 = ws[384 + i * 32 + lane];
            #pragma unroll
            for (int r = 0; r < RQ; r++) {
                float4 t = xv[r];
                a[r][0] = fmaf(t.x, w0.x, fmaf(t.y, w0.y, fmaf(t.z, w0.z, fmaf(t.w, w0.w, a[r][0]))));
                a[r][1] = fmaf(t.x, w1.x, fmaf(t.y, w1.y, fmaf(t.z, w1.z, fmaf(t.w, w1.w, a[r][1]))));
                a[r][2] = fmaf(t.x, w2.x, fmaf(t.y, w2.y, fmaf(t.z, w2.z, fmaf(t.w, w2.w, a[r][2]))));
            }
        }

        #pragma unroll
        for (int off = 16; off; off >>= 1) {
            #pragma unroll
            for (int r = 0; r < RQ; r++) {
                a[r][0] += __shfl_xor_sync(FULLM, a[r][0], off);
                a[r][1] += __shfl_xor_sync(FULLM, a[r][1], off);
                a[r][2] += __shfl_xor_sync(FULLM, a[r][2], off);
            }
        }
        if (lane < RQ) {
            float* o = out + (size_t)(row0 + lane) * 3;
            o[0] = a[lane][0] + bs[0];
            o[1] = a[lane][1] + bs[1];
            o[2] = a[lane][2] + bs[2];
        }
    }
#if __CUDA_ARCH__ >= 900
    cudaTriggerProgrammaticLaunchCompletion();
#endif
}

// -------------------- kernel 2: CRF, 2 warps per batch --------------------
__device__ __forceinline__ void renorm9(float a[9], float& ls) {
    float m = a[0];
    #pragma unroll
    for (int e = 1; e < 9; e++) m = fmaxf(m, a[e]);
    int eb = (__float_as_int(m) >> 23) - 127;
    float s = __int_as_float((127 - eb) << 23);   // exact 2^-eb
    #pragma unroll
    for (int e = 0; e < 9; e++) a[e] *= s;
    ls += (float)eb * LN2F;
}

__global__ __launch_bounds__(64) void crf_kernel(
    const float* __restrict__ pred, const void* __restrict__ yraw,
    const float* __restrict__ trans, const float* __restrict__ start_t,
    const float* __restrict__ stop_t, float* __restrict__ loss_out)
{
    __shared__ float tr_s[9], st_s[3], sp_s[3];
    __shared__ float hm[9];
    __shared__ float hls;
    __shared__ float gred[2];
    __shared__ int s_last;

    int b    = blockIdx.x;
    int tid  = threadIdx.x;         // 0..63
    int w    = tid >> 5;
    int lane = tid & 31;

    // ---- prologue: everything independent of pred output ----
    if (tid < 9) tr_s[tid] = trans[tid];
    if (tid < 3) { st_s[tid] = start_t[tid]; sp_s[tid] = stop_t[tid]; }

    // y dtype sniff per warp (values 0..2; LE int64 -> odd 32-bit words zero)
    const int* yw = (const int*)yraw;
    int oddw = (lane < 16) ? yw[2 * lane + 1] : 0;
    int stride = (__ballot_sync(FULLM, oddw != 0) == 0u) ? 2 : 1;
    const int* yb = yw + (size_t)b * S_LEN * stride;

    int t0 = tid * SEG;             // 64 lanes x 8 steps = 512

    int tg[SEG];
    #pragma unroll
    for (int k = 0; k < SEG; k++) tg[k] = yb[(t0 + k) * stride];
    int tprev = (tid > 0) ? yb[(t0 - 1) * stride] : 0;

    __syncthreads();                // tr_s/st_s/sp_s visible
    float etr[9];
    #pragma unroll
    for (int j = 0; j < 9; j++) etr[j] = __expf(tr_s[j]);

#if __CUDA_ARCH__ >= 900
    cudaGridDependencySynchronize();   // pred output ready beyond this point
#endif

    // ---- feats for this lane's 8 timesteps (24 floats, 16B-aligned) ----
    float f[3 * SEG];
    const float4* pf = reinterpret_cast<const float4*>(
        pred + (size_t)b * S_LEN * 3 + (size_t)t0 * 3);
    #pragma unroll
    for (int i = 0; i < 6; i++) {
        float4 v = pf[i];
        f[4*i] = v.x; f[4*i+1] = v.y; f[4*i+2] = v.z; f[4*i+3] = v.w;
    }

    // ---- gold path partial ----
    float gold = 0.f;
    #pragma unroll
    for (int k = 0; k < SEG; k++) {
        int t = tg[k];
        gold += (t == 0) ? f[3*k] : ((t == 1) ? f[3*k+1] : f[3*k+2]);
        int tp = (k == 0) ? tprev : tg[k-1];
        if (t0 + k > 0) gold += tr_s[tp * 3 + t];
    }
    if (tid == 0)  gold += st_s[tg[0]];
    if (tid == 63) gold += sp_s[tg[SEG-1]];
    #pragma unroll
    for (int off = 16; off; off >>= 1) gold += __shfl_xor_sync(FULLM, gold, off);
    if (lane == 0) gred[w] = gold;

    // ---- sequential chain of 8 leaves (linear domain, exact pow2 renorm) ----
    float a[9], ls;
    {
        float f0 = f[0], f1 = f[1], f2 = f[2];
        if (tid == 0) { f0 += st_s[0]; f1 += st_s[1]; f2 += st_s[2]; }
        float c = fmaxf(f0, fmaxf(f1, f2));
        float e0 = __expf(f0 - c), e1 = __expf(f1 - c), e2 = __expf(f2 - c);
        ls = c;
        if (tid == 0) {             // rank-1 a0 leaf
            a[0]=e0; a[1]=e1; a[2]=e2; a[3]=e0; a[4]=e1; a[5]=e2; a[6]=e0; a[7]=e1; a[8]=e2;
        } else {
            #pragma unroll
            for (int i = 0; i < 3; i++) {
                a[i*3+0] = etr[i*3+0] * e0;
                a[i*3+1] = etr[i*3+1] * e1;
                a[i*3+2] = etr[i*3+2] * e2;
            }
        }
    }
    #pragma unroll
    for (int k = 1; k < SEG; k++) {
        float f0 = f[3*k], f1 = f[3*k+1], f2 = f[3*k+2];
        float c = fmaxf(f0, fmaxf(f1, f2));
        float e0 = __expf(f0 - c), e1 = __expf(f1 - c), e2 = __expf(f2 - c);
        ls += c;
        float n[9];
        #pragma unroll
        for (int i = 0; i < 3; i++) {
            n[i*3+0] = fmaf(a[i*3], etr[0], fmaf(a[i*3+1], etr[3], a[i*3+2] * etr[6])) * e0;
            n[i*3+1] = fmaf(a[i*3], etr[1], fmaf(a[i*3+1], etr[4], a[i*3+2] * etr[7])) * e1;
            n[i*3+2] = fmaf(a[i*3], etr[2], fmaf(a[i*3+1], etr[5], a[i*3+2] * etr[8])) * e2;
        }
        #pragma unroll
        for (int e = 0; e < 9; e++) a[e] = n[e];
        if ((k & 3) == 3) renorm9(a, ls);
    }

    // ---- intra-warp order-preserving shuffle tree (5 levels) ----
    #pragma unroll
    for (int off = 1; off < 32; off <<= 1) {
        float bm[9];
        #pragma unroll
        for (int e = 0; e < 9; e++) bm[e] = __shfl_down_sync(FULLM, a[e], off);
        float lsb = __shfl_down_sync(FULLM, ls, off);
        if ((lane & (2 * off - 1)) == 0) {
            float n[9];
            #pragma unroll
            for (int i = 0; i < 3; i++) {
                n[i*3+0] = fmaf(a[i*3], bm[0], fmaf(a[i*3+1], bm[3], a[i*3+2] * bm[6]));
                n[i*3+1] = fmaf(a[i*3], bm[1], fmaf(a[i*3+1], bm[4], a[i*3+2] * bm[7]));
                n[i*3+2] = fmaf(a[i*3], bm[2], fmaf(a[i*3+1], bm[5], a[i*3+2] * bm[8]));
            }
            #pragma unroll
            for (int e = 0; e < 9; e++) a[e] = n[e];
            ls += lsb;
            renorm9(a, ls);
        }
    }

    // warp1's half-product -> smem; tid0 combines (order: warp0 x warp1)
    if (tid == 32) {
        #pragma unroll
        for (int e = 0; e < 9; e++) hm[e] = a[e];
        hls = ls;
    }
    __syncthreads();

    if (tid == 0) {
        float n[9];
        #pragma unroll
        for (int i = 0; i < 3; i++) {
            n[i*3+0] = fmaf(a[i*3], hm[0], fmaf(a[i*3+1], hm[3], a[i*3+2] * hm[6]));
            n[i*3+1] = fmaf(a[i*3], hm[1], fmaf(a[i*3+1], hm[4], a[i*3+2] * hm[7]));
            n[i*3+2] = fmaf(a[i*3], hm[2], fmaf(a[i*3+1], hm[5], a[i*3+2] * hm[8]));
        }
        float lst = ls + hls;
        renorm9(n, lst);
        float z = n[0] * __expf(sp_s[0]) + n[1] * __expf(sp_s[1]) + n[2] * __expf(sp_s[2]);
        g_part[b] = (gred[0] + gred[1]) - (lst + __logf(z));
    }

    // ---- fused finalize: last block reduces all 128 partials ----
    if (tid == 0) {
        __threadfence();
        s_last = ((int)atomicAdd(&g_done, 1) == B_SZ - 1);
    }
    __syncthreads();
    if (s_last && w == 0) {
        __threadfence();
        float s = __ldcg(&g_part[lane])      + __ldcg(&g_part[lane + 32])
                + __ldcg(&g_part[lane + 64]) + __ldcg(&g_part[lane + 96]);
        #pragma unroll
        for (int off = 16; off; off >>= 1) s += __shfl_xor_sync(FULLM, s, off);
        if (lane == 0) {
            *loss_out = -s / (float)B_SZ;
            g_done = 0;                      // self-reset for next graph replay
        }
    }
}

// -------------------- launch --------------------
extern "C" void kernel_launch(void* const* d_in, const int* in_sizes, int n_in,
                              void* d_out, int out_size)
{
    const float* x     = (const float*)d_in[0];
    const void*  y     = d_in[1];
    const float* W     = (const float*)d_in[2];
    const float* bias  = (const float*)d_in[3];
    const float* trans = (const float*)d_in[4];
    const float* st    = (const float*)d_in[5];
    const float* sp    = (const float*)d_in[6];
    float* out = (float*)d_out;

    int nrows = in_sizes[0] / H_DIM;    // 65536

    pred_kernel<<<PRED_BLOCKS, PRED_THREADS>>>(x, W, bias, out, nrows);

    // crf with PDL: prologue overlaps pred tail; gridDependencySynchronize
    // guards the feats read. Falls back to serial execution semantics if the
    // attribute is not honored (still correct).
    cudaLaunchConfig_t cfg = {};
    cfg.gridDim  = dim3(B_SZ);
    cfg.blockDim = dim3(64);
    cfg.dynamicSmemBytes = 0;
    cfg.stream = 0;
    cudaLaunchAttribute attr[1];
    attr[0].id = cudaLaunchAttributeProgrammaticStreamSerialization;
    attr[0].val.programmaticStreamSerializationAllowed = 1;
    cfg.attrs = attr;
    cfg.numAttrs = 1;
    cudaLaunchKernelEx(&cfg, crf_kernel,
                       (const float*)out, (const void*)y, trans, st, sp,
                       out + (out_size - 1));
}

// round 9
// speedup vs baseline: 1.2428x; 1.0067x over previous
#include <cuda_runtime.h>
#include <cuda_bf16.h>
#include <math.h>

#define H_DIM 768
#define S_LEN 512
#define B_SZ 128
#define F4_PER_ROW (H_DIM / 4)      // 192
#define CHUNKS (H_DIM / 128)        // 6
#define RQ 4
#define QPW 4
#define THREADS 128                 // 4 warps -> 8 blocks/SM -> single wave
#define BLOCKS 1024                 // 64 rows/block; 8 blocks per batch
#define SEG 4                       // 128 lanes x 4 timesteps = 512
#define LN2F 0.6931471805599453f
#define FULLM 0xffffffffu

__device__ float g_part[B_SZ];
__device__ unsigned int g_cnt[B_SZ];   // zero-init; consumer resets its slot
__device__ unsigned int g_done;        // zero-init; finalizer resets

union SmemU {
    struct { float4 ws[3 * F4_PER_ROW]; float bs[3]; } pred;   // 9.2 KB
    struct {
        float tr[9], st[3], sp[3];
        float gm[4][9];   // per-warp partial chain products
        float gls[4];     // per-warp log-scales
        float gsum[4];    // per-warp gold partials
        float fin[4];     // finalize warp partials (unused slots ok)
    } crf;
};

__device__ __forceinline__ void renorm9(float a[9], float& ls) {
    float m = a[0];
    #pragma unroll
    for (int e = 1; e < 9; e++) m = fmaxf(m, a[e]);
    int eb = (__float_as_int(m) >> 23) - 127;
    float s = __int_as_float((127 - eb) << 23);   // exact 2^-eb
    #pragma unroll
    for (int e = 0; e < 9; e++) a[e] *= s;
    ls += (float)eb * LN2F;
}

__device__ __forceinline__ void mm3(const float a[9], const float b[9], float n[9]) {
    #pragma unroll
    for (int i = 0; i < 3; i++) {
        n[i*3+0] = fmaf(a[i*3], b[0], fmaf(a[i*3+1], b[3], a[i*3+2] * b[6]));
        n[i*3+1] = fmaf(a[i*3], b[1], fmaf(a[i*3+1], b[4], a[i*3+2] * b[7]));
        n[i*3+2] = fmaf(a[i*3], b[2], fmaf(a[i*3+1], b[5], a[i*3+2] * b[8]));
    }
}

// ---------------- inline CRF for one batch: 128 lanes x 4 timesteps ----------------
__device__ void crf_inline(
    SmemU& sm, int b, const float* __restrict__ pred, const void* __restrict__ yraw,
    const float* __restrict__ trans, const float* __restrict__ start_t,
    const float* __restrict__ stop_t, float* __restrict__ loss_out)
{
    auto& C = sm.crf;
    int tid  = threadIdx.x;
    int w    = tid >> 5;
    int lane = tid & 31;

    if (tid < 9) C.tr[tid] = trans[tid];
    if (tid < 3) { C.st[tid] = start_t[tid]; C.sp[tid] = stop_t[tid]; }

    // y dtype sniff (values 0..2; LE int64 -> odd 32-bit words zero)
    const int* yw = (const int*)yraw;
    int oddw = (lane < 16) ? yw[2 * lane + 1] : 0;
    int stride = (__ballot_sync(FULLM, oddw != 0) == 0u) ? 2 : 1;
    const int* yb = yw + (size_t)b * S_LEN * stride;

    int t0 = tid * SEG;
    int tg[SEG];
    #pragma unroll
    for (int k = 0; k < SEG; k++) tg[k] = yb[(t0 + k) * stride];
    int tprev = (tid > 0) ? yb[(t0 - 1) * stride] : 0;

    // feats: 12 floats = 3 float4 per lane (other blocks' writes -> __ldcg)
    float f[3 * SEG];
    const float4* pf = reinterpret_cast<const float4*>(
        pred + (size_t)b * S_LEN * 3 + (size_t)t0 * 3);
    #pragma unroll
    for (int i = 0; i < 3; i++) {
        float4 v = __ldcg(&pf[i]);
        f[4*i] = v.x; f[4*i+1] = v.y; f[4*i+2] = v.z; f[4*i+3] = v.w;
    }
    __syncthreads();   // C.tr/st/sp visible

    float etr[9];
    #pragma unroll
    for (int j = 0; j < 9; j++) etr[j] = __expf(C.tr[j]);

    // ---- gold path partial ----
    float gold = 0.f;
    #pragma unroll
    for (int k = 0; k < SEG; k++) {
        int t = tg[k];
        gold += (t == 0) ? f[3*k] : ((t == 1) ? f[3*k+1] : f[3*k+2]);
        int tp = (k == 0) ? tprev : tg[k-1];
        if (t0 + k > 0) gold += C.tr[tp * 3 + t];
    }
    if (tid == 0)   gold += C.st[tg[0]];
    if (tid == 127) gold += C.sp[tg[SEG-1]];
    #pragma unroll
    for (int off = 16; off; off >>= 1) gold += __shfl_xor_sync(FULLM, gold, off);
    if (lane == 0) C.gsum[w] = gold;

    // ---- chain of 4 leaves (linear domain) ----
    float a[9], ls;
    {
        float f0 = f[0], f1 = f[1], f2 = f[2];
        if (tid == 0) { f0 += C.st[0]; f1 += C.st[1]; f2 += C.st[2]; }
        float c = fmaxf(f0, fmaxf(f1, f2));
        float e0 = __expf(f0 - c), e1 = __expf(f1 - c), e2 = __expf(f2 - c);
        ls = c;
        if (tid == 0) {            // rank-1 a0 leaf
            a[0]=e0; a[1]=e1; a[2]=e2; a[3]=e0; a[4]=e1; a[5]=e2; a[6]=e0; a[7]=e1; a[8]=e2;
        } else {
            #pragma unroll
            for (int i = 0; i < 3; i++) {
                a[i*3+0] = etr[i*3+0] * e0;
                a[i*3+1] = etr[i*3+1] * e1;
                a[i*3+2] = etr[i*3+2] * e2;
            }
        }
    }
    #pragma unroll
    for (int k = 1; k < SEG; k++) {
        float f0 = f[3*k], f1 = f[3*k+1], f2 = f[3*k+2];
        float c = fmaxf(f0, fmaxf(f1, f2));
        float e0 = __expf(f0 - c), e1 = __expf(f1 - c), e2 = __expf(f2 - c);
        ls += c;
        float n[9];
        #pragma unroll
        for (int i = 0; i < 3; i++) {
            n[i*3+0] = fmaf(a[i*3], etr[0], fmaf(a[i*3+1], etr[3], a[i*3+2] * etr[6])) * e0;
            n[i*3+1] = fmaf(a[i*3], etr[1], fmaf(a[i*3+1], etr[4], a[i*3+2] * etr[7])) * e1;
            n[i*3+2] = fmaf(a[i*3], etr[2], fmaf(a[i*3+1], etr[5], a[i*3+2] * etr[8])) * e2;
        }
        #pragma unroll
        for (int e = 0; e < 9; e++) a[e] = n[e];
    }
    renorm9(a, ls);

    // ---- intra-warp order-preserving shuffle tree ----
    #pragma unroll
    for (int off = 1; off < 32; off <<= 1) {
        float bm[9];
        #pragma unroll
        for (int e = 0; e < 9; e++) bm[e] = __shfl_down_sync(FULLM, a[e], off);
        float lsb = __shfl_down_sync(FULLM, ls, off);
        if ((lane & (2 * off - 1)) == 0) {
            float n[9];
            mm3(a, bm, n);
            #pragma unroll
            for (int e = 0; e < 9; e++) a[e] = n[e];
            ls += lsb;
            renorm9(a, ls);
        }
    }
    if (lane == 0) {
        #pragma unroll
        for (int e = 0; e < 9; e++) C.gm[w][e] = a[e];
        C.gls[w] = ls;
    }
    __syncthreads();

    if (tid == 0) {
        float p[9], n[9];
        #pragma unroll
        for (int e = 0; e < 9; e++) p[e] = C.gm[0][e];
        float lst = C.gls[0];
        #pragma unroll
        for (int wj = 1; wj < 4; wj++) {
            mm3(p, C.gm[wj], n);
            #pragma unroll
            for (int e = 0; e < 9; e++) p[e] = n[e];
            lst += C.gls[wj];
            renorm9(p, lst);
        }
        float z = p[0] * __expf(C.sp[0]) + p[1] * __expf(C.sp[1]) + p[2] * __expf(C.sp[2]);
        float goldt = C.gsum[0] + C.gsum[1] + C.gsum[2] + C.gsum[3];
        g_part[b] = goldt - (lst + __logf(z));
        g_cnt[b] = 0;                        // self-reset for next graph replay
    }

    // ---- finalize: 128th batch-completer reduces all partials ----
    __shared__ int s_last;
    if (tid == 0) {
        __threadfence();
        s_last = ((int)atomicAdd(&g_done, 1) == B_SZ - 1);
    }
    __syncthreads();
    if (s_last && w == 0) {
        __threadfence();
        float s = __ldcg(&g_part[lane])      + __ldcg(&g_part[lane + 32])
                + __ldcg(&g_part[lane + 64]) + __ldcg(&g_part[lane + 96]);
        #pragma unroll
        for (int off = 16; off; off >>= 1) s += __shfl_xor_sync(FULLM, s, off);
        if (lane == 0) {
            *loss_out = -s / (float)B_SZ;
            g_done = 0;                      // self-reset for next graph replay
        }
    }
}

// ---------------- fused kernel ----------------
__global__ __launch_bounds__(THREADS, 8) void fused_kernel(
    const float* __restrict__ x, const void* __restrict__ yraw,
    const float* __restrict__ W, const float* __restrict__ bias,
    const float* __restrict__ trans, const float* __restrict__ start_t,
    const float* __restrict__ stop_t, float* __restrict__ out,
    int nrows, int out_size)
{
    __shared__ SmemU sm;
    __shared__ int s_is_last_producer;
    int tid = threadIdx.x;

    // -------- pred body: 64 rows (R6 inner loop, proven) --------
    {
        auto& P = sm.pred;
        for (int i = tid; i < 3 * F4_PER_ROW; i += THREADS)
            P.ws[i] = reinterpret_cast<const float4*>(W)[i];
        if (tid < 3) P.bs[tid] = bias[tid];
        __syncthreads();

        int lane = tid & 31;
        int gw   = blockIdx.x * (THREADS / 32) + (tid >> 5);

        #pragma unroll
        for (int q = 0; q < QPW; q++) {
            int row0 = gw * (QPW * RQ) + q * RQ;
            if (row0 >= nrows) break;
            const float4* xr = reinterpret_cast<const float4*>(x)
                               + (size_t)row0 * F4_PER_ROW + lane;

            float a[RQ][3];
            #pragma unroll
            for (int r = 0; r < RQ; r++) { a[r][0] = 0.f; a[r][1] = 0.f; a[r][2] = 0.f; }

            #pragma unroll
            for (int i = 0; i < CHUNKS; i++) {
                float4 xv[RQ];
                #pragma unroll
                for (int r = 0; r < RQ; r++)
                    xv[r] = __ldcs(&xr[(size_t)r * F4_PER_ROW + i * 32]);
                float4 w0 = P.ws[i * 32 + lane];
                float4 w1 = P.ws[192 + i * 32 + lane];
                float4 w2 = P.ws[384 + i * 32 + lane];
                #pragma unroll
                for (int r = 0; r < RQ; r++) {
                    float4 t = xv[r];
                    a[r][0] = fmaf(t.x, w0.x, fmaf(t.y, w0.y, fmaf(t.z, w0.z, fmaf(t.w, w0.w, a[r][0]))));
                    a[r][1] = fmaf(t.x, w1.x, fmaf(t.y, w1.y, fmaf(t.z, w1.z, fmaf(t.w, w1.w, a[r][1]))));
                    a[r][2] = fmaf(t.x, w2.x, fmaf(t.y, w2.y, fmaf(t.z, w2.z, fmaf(t.w, w2.w, a[r][2]))));
                }
            }

            #pragma unroll
            for (int off = 16; off; off >>= 1) {
                #pragma unroll
                for (int r = 0; r < RQ; r++) {
                    a[r][0] += __shfl_xor_sync(FULLM, a[r][0], off);
                    a[r][1] += __shfl_xor_sync(FULLM, a[r][1], off);
                    a[r][2] += __shfl_xor_sync(FULLM, a[r][2], off);
                }
            }
            if (lane < RQ) {
                float* o = out + (size_t)(row0 + lane) * 3;
                o[0] = a[lane][0] + P.bs[0];
                o[1] = a[lane][1] + P.bs[1];
                o[2] = a[lane][2] + P.bs[2];
            }
        }
    }

    // -------- per-batch completion: last of 8 producers runs the CRF inline --------
    int b = blockIdx.x >> 3;            // 8 blocks x 64 rows = 512 rows per batch
    __syncthreads();                    // all stores of this block issued
    if (tid == 0) {
        __threadfence();                // publish this block's rows
        s_is_last_producer = (atomicAdd(&g_cnt[b], 1) == 7);
    }
    __syncthreads();
    if (!s_is_last_producer) return;

    __threadfence();                    // acquire: other producers' rows visible
    crf_inline(sm, b, out, yraw, trans, start_t, stop_t, out + (out_size - 1));
}

// ---------------- launch ----------------
extern "C" void kernel_launch(void* const* d_in, const int* in_sizes, int n_in,
                              void* d_out, int out_size)
{
    const float* x     = (const float*)d_in[0];
    const void*  y     = d_in[1];
    const float* W     = (const float*)d_in[2];
    const float* bias  = (const float*)d_in[3];
    const float* trans = (const float*)d_in[4];
    const float* st    = (const float*)d_in[5];
    const float* sp    = (const float*)d_in[6];
    float* out = (float*)d_out;

    int nrows = in_sizes[0] / H_DIM;    // 65536

    fused_kernel<<<BLOCKS, THREADS>>>(x, y, W, bias, trans, st, sp,
                                      out, nrows, out_size);
}

// round 10
// speedup vs baseline: 1.2483x; 1.0045x over previous
#include <cuda_runtime.h>
#include <cuda_bf16.h>
#include <math.h>

#define H_DIM 768
#define S_LEN 512
#define B_SZ 128
#define F4_PER_ROW (H_DIM / 4)      // 192
#define CHUNKS (H_DIM / 128)        // 6
#define RQ 4
#define QPW 4
#define THREADS 128                 // 4 warps; 8 blocks/SM -> single resident wave
#define BLOCKS 1024                 // 64 rows/block; 8 blocks per batch
#define LN2F 0.6931471805599453f
#define FULLM 0xffffffffu

// Per-block CRF partials (written during the wave, combined in the tail)
__device__ float g_sm_[BLOCKS][9];
__device__ float g_sls[BLOCKS];
__device__ float g_sg[BLOCKS];
__device__ float g_part[B_SZ];
__device__ unsigned int g_cnt[B_SZ];   // zero-init; combiner resets its slot
__device__ unsigned int g_done;        // zero-init; finalizer resets

__device__ __forceinline__ void renorm9(float a[9], float& ls) {
    float m = a[0];
    #pragma unroll
    for (int e = 1; e < 9; e++) m = fmaxf(m, a[e]);
    int eb = (__float_as_int(m) >> 23) - 127;
    float s = __int_as_float((127 - eb) << 23);   // exact 2^-eb
    #pragma unroll
    for (int e = 0; e < 9; e++) a[e] *= s;
    ls += (float)eb * LN2F;
}

__device__ __forceinline__ void mm3(const float a[9], const float b[9], float n[9]) {
    #pragma unroll
    for (int i = 0; i < 3; i++) {
        n[i*3+0] = fmaf(a[i*3], b[0], fmaf(a[i*3+1], b[3], a[i*3+2] * b[6]));
        n[i*3+1] = fmaf(a[i*3], b[1], fmaf(a[i*3+1], b[4], a[i*3+2] * b[7]));
        n[i*3+2] = fmaf(a[i*3], b[2], fmaf(a[i*3+1], b[5], a[i*3+2] * b[8]));
    }
}

__global__ __launch_bounds__(THREADS, 8) void fused_kernel(
    const float* __restrict__ x, const void* __restrict__ yraw,
    const float* __restrict__ W, const float* __restrict__ bias,
    const float* __restrict__ trans, const float* __restrict__ start_t,
    const float* __restrict__ stop_t, float* __restrict__ out,
    int nrows, int out_size)
{
    __shared__ float4 ws[3 * F4_PER_ROW];   // 9 KB
    __shared__ float bs[3];
    __shared__ float feats_sm[64 * 3];      // this block's 64 rows of output
    __shared__ float tr_sm[9], etr_sm[9], st_sm[3], sp_sm[3];
    __shared__ float wm[2][9], wls[2], wgold[2];
    __shared__ int s_flag;

    int tid  = threadIdx.x;
    int lane = tid & 31;
    int w    = tid >> 5;

    for (int i = tid; i < 3 * F4_PER_ROW; i += THREADS)
        ws[i] = reinterpret_cast<const float4*>(W)[i];
    if (tid < 9) { float t = trans[tid]; tr_sm[tid] = t; etr_sm[tid] = __expf(t); }
    if (tid < 3) { bs[tid] = bias[tid]; st_sm[tid] = start_t[tid]; sp_sm[tid] = stop_t[tid]; }
    __syncthreads();

    // ---------------- pred: 64 rows (proven R6 inner loop) ----------------
    int gw = blockIdx.x * 4 + w;
    #pragma unroll
    for (int q = 0; q < QPW; q++) {
        int row0 = gw * (QPW * RQ) + q * RQ;
        if (row0 >= nrows) break;
        const float4* xr = reinterpret_cast<const float4*>(x)
                           + (size_t)row0 * F4_PER_ROW + lane;

        float a[RQ][3];
        #pragma unroll
        for (int r = 0; r < RQ; r++) { a[r][0] = 0.f; a[r][1] = 0.f; a[r][2] = 0.f; }

        #pragma unroll
        for (int i = 0; i < CHUNKS; i++) {
            float4 xv[RQ];
            #pragma unroll
            for (int r = 0; r < RQ; r++)
                xv[r] = __ldcs(&xr[(size_t)r * F4_PER_ROW + i * 32]);
            float4 w0 = ws[i * 32 + lane];
            float4 w1 = ws[192 + i * 32 + lane];
            float4 w2 = ws[384 + i * 32 + lane];
            #pragma unroll
            for (int r = 0; r < RQ; r++) {
                float4 t = xv[r];
                a[r][0] = fmaf(t.x, w0.x, fmaf(t.y, w0.y, fmaf(t.z, w0.z, fmaf(t.w, w0.w, a[r][0]))));
                a[r][1] = fmaf(t.x, w1.x, fmaf(t.y, w1.y, fmaf(t.z, w1.z, fmaf(t.w, w1.w, a[r][1]))));
                a[r][2] = fmaf(t.x, w2.x, fmaf(t.y, w2.y, fmaf(t.z, w2.z, fmaf(t.w, w2.w, a[r][2]))));
            }
        }

        #pragma unroll
        for (int off = 16; off; off >>= 1) {
            #pragma unroll
            for (int r = 0; r < RQ; r++) {
                a[r][0] += __shfl_xor_sync(FULLM, a[r][0], off);
                a[r][1] += __shfl_xor_sync(FULLM, a[r][1], off);
                a[r][2] += __shfl_xor_sync(FULLM, a[r][2], off);
            }
        }
        if (lane < RQ) {
            float v0 = a[lane][0] + bs[0];
            float v1 = a[lane][1] + bs[1];
            float v2 = a[lane][2] + bs[2];
            float* o = out + (size_t)(row0 + lane) * 3;
            o[0] = v0; o[1] = v1; o[2] = v2;
            int tl = w * 16 + q * 4 + lane;        // local timestep 0..63
            feats_sm[tl * 3 + 0] = v0;
            feats_sm[tl * 3 + 1] = v1;
            feats_sm[tl * 3 + 2] = v2;
        }
    }
    __syncthreads();

    // ---------------- per-block CRF partial (overlaps other blocks' pred) ----------------
    int b       = blockIdx.x >> 3;           // batch
    int tb_base = (blockIdx.x & 7) * 64;     // this block's first timestep in batch

    if (w < 2) {
        // warps 0,1: chain product of 32 leaves each (1 timestep per lane)
        int tl = w * 32 + lane;
        int tb = tb_base + tl;
        float f0 = feats_sm[tl*3], f1 = feats_sm[tl*3+1], f2 = feats_sm[tl*3+2];
        if (tb == 0) { f0 += st_sm[0]; f1 += st_sm[1]; f2 += st_sm[2]; }
        float c  = fmaxf(f0, fmaxf(f1, f2));
        float e0 = __expf(f0 - c), e1 = __expf(f1 - c), e2 = __expf(f2 - c);
        float a[9]; float ls = c;
        if (tb == 0) {                        // rank-1 a0 leaf
            a[0]=e0; a[1]=e1; a[2]=e2; a[3]=e0; a[4]=e1; a[5]=e2; a[6]=e0; a[7]=e1; a[8]=e2;
        } else {
            #pragma unroll
            for (int i = 0; i < 3; i++) {
                a[i*3+0] = etr_sm[i*3+0] * e0;
                a[i*3+1] = etr_sm[i*3+1] * e1;
                a[i*3+2] = etr_sm[i*3+2] * e2;
            }
        }
        // ordered shuffle tree: lane i ends with product of [i, i+2off)
        #pragma unroll
        for (int off = 1; off < 32; off <<= 1) {
            float bm[9];
            #pragma unroll
            for (int e = 0; e < 9; e++) bm[e] = __shfl_down_sync(FULLM, a[e], off);
            float lsb = __shfl_down_sync(FULLM, ls, off);
            if ((lane & (2 * off - 1)) == 0) {
                float n[9];
                mm3(a, bm, n);
                #pragma unroll
                for (int e = 0; e < 9; e++) a[e] = n[e];
                ls += lsb;
                renorm9(a, ls);
            }
        }
        if (lane == 0) {
            #pragma unroll
            for (int e = 0; e < 9; e++) wm[w][e] = a[e];
            wls[w] = ls;
        }
    } else {
        // warps 2,3: gold-path partial (1 timestep per lane)
        int tl = (w - 2) * 32 + lane;
        int tb = tb_base + tl;
        // y dtype sniff (values 0..2; LE int64 -> odd 32-bit words zero)
        const int* yw = (const int*)yraw;
        int oddw = (lane < 16) ? yw[2 * lane + 1] : 0;
        int stride = (__ballot_sync(FULLM, oddw != 0) == 0u) ? 2 : 1;
        const int* yb = yw + (size_t)b * S_LEN * stride;

        int tg = yb[tb * stride];
        float g = feats_sm[tl * 3 + tg];
        if (tb > 0) { int tp = yb[(tb - 1) * stride]; g += tr_sm[tp * 3 + tg]; }
        else         g += st_sm[tg];
        if (tb == S_LEN - 1) g += sp_sm[tg];
        #pragma unroll
        for (int off = 16; off; off >>= 1) g += __shfl_xor_sync(FULLM, g, off);
        if (lane == 0) wgold[w - 2] = g;
    }
    __syncthreads();

    if (tid == 0) {
        float p[9];
        mm3(wm[0], wm[1], p);
        float ls = wls[0] + wls[1];
        renorm9(p, ls);
        #pragma unroll
        for (int e = 0; e < 9; e++) g_sm_[blockIdx.x][e] = p[e];
        g_sls[blockIdx.x] = ls;
        g_sg[blockIdx.x]  = wgold[0] + wgold[1];
        __threadfence();
        s_flag = (atomicAdd(&g_cnt[b], 1) == 7);
    }
    __syncthreads();
    if (!s_flag) return;

    // ---------------- batch combine: ordered product of 8 block partials ----------------
    if (tid == 0) {
        __threadfence();                     // acquire other producers' scratch
        int base = b * 8;
        float p[9], n[9], q9[9];
        #pragma unroll
        for (int e = 0; e < 9; e++) p[e] = __ldcg(&g_sm_[base][e]);
        float ls   = __ldcg(&g_sls[base]);
        float gold = __ldcg(&g_sg[base]);
        #pragma unroll
        for (int j = 1; j < 8; j++) {
            #pragma unroll
            for (int e = 0; e < 9; e++) q9[e] = __ldcg(&g_sm_[base + j][e]);
            mm3(p, q9, n);
            #pragma unroll
            for (int e = 0; e < 9; e++) p[e] = n[e];
            ls += __ldcg(&g_sls[base + j]);
            renorm9(p, ls);
            gold += __ldcg(&g_sg[base + j]);
        }
        float z = p[0] * __expf(sp_sm[0]) + p[1] * __expf(sp_sm[1]) + p[2] * __expf(sp_sm[2]);
        g_part[b] = gold - (ls + __logf(z));
        g_cnt[b] = 0;                        // self-reset for next graph replay
        __threadfence();
        s_flag = ((int)atomicAdd(&g_done, 1) == B_SZ - 1);
    }
    __syncthreads();

    // ---------------- finalize: 128th batch-completer reduces all partials ----------------
    if (s_flag && w == 0) {
        __threadfence();
        float s = __ldcg(&g_part[lane])      + __ldcg(&g_part[lane + 32])
                + __ldcg(&g_part[lane + 64]) + __ldcg(&g_part[lane + 96]);
        #pragma unroll
        for (int off = 16; off; off >>= 1) s += __shfl_xor_sync(FULLM, s, off);
        if (lane == 0) {
            out[out_size - 1] = -s / (float)B_SZ;
            g_done = 0;                      // self-reset for next graph replay
        }
    }
}

// ---------------- launch ----------------
extern "C" void kernel_launch(void* const* d_in, const int* in_sizes, int n_in,
                              void* d_out, int out_size)
{
    const float* x     = (const float*)d_in[0];
    const void*  y     = d_in[1];
    const float* W     = (const float*)d_in[2];
    const float* bias  = (const float*)d_in[3];
    const float* trans = (const float*)d_in[4];
    const float* st    = (const float*)d_in[5];
    const float* sp    = (const float*)d_in[6];
    float* out = (float*)d_out;

    int nrows = in_sizes[0] / H_DIM;    // 65536

    fused_kernel<<<BLOCKS, THREADS>>>(x, y, W, bias, trans, st, sp,
                                      out, nrows, out_size);
}

// round 11
// speedup vs baseline: 1.2955x; 1.0378x over previous
#include <cuda_runtime.h>
#include <cuda_bf16.h>
#include <math.h>

#define H_DIM 768
#define S_LEN 512
#define B_SZ 128
#define F4_PER_ROW (H_DIM / 4)      // 192
#define CHUNKS (H_DIM / 128)        // 6
#define RQ 4
#define QPW 4                       // quads per warp: 16 rows/warp
#define THREADS 256                 // 8 warps -> 128 rows/block
#define BLOCKS 512                  // 512 blocks <= 608 slots: ONE resident wave
#define LN2F 0.6931471805599453f
#define FULLM 0xffffffffu

// Per-block CRF partials (block = quarter batch)
__device__ float g_sm_[BLOCKS][9];
__device__ float g_sls[BLOCKS];
__device__ float g_sg[BLOCKS];
__device__ float g_part[B_SZ];
__device__ unsigned int g_cnt[B_SZ];   // zero-init; combiner resets its slot
__device__ unsigned int g_done;        // zero-init; finalizer resets

__device__ __forceinline__ void renorm9(float a[9], float& ls) {
    float m = a[0];
    #pragma unroll
    for (int e = 1; e < 9; e++) m = fmaxf(m, a[e]);
    int eb = (__float_as_int(m) >> 23) - 127;
    float s = __int_as_float((127 - eb) << 23);   // exact 2^-eb
    #pragma unroll
    for (int e = 0; e < 9; e++) a[e] *= s;
    ls += (float)eb * LN2F;
}

__device__ __forceinline__ void mm3(const float a[9], const float b[9], float n[9]) {
    #pragma unroll
    for (int i = 0; i < 3; i++) {
        n[i*3+0] = fmaf(a[i*3], b[0], fmaf(a[i*3+1], b[3], a[i*3+2] * b[6]));
        n[i*3+1] = fmaf(a[i*3], b[1], fmaf(a[i*3+1], b[4], a[i*3+2] * b[7]));
        n[i*3+2] = fmaf(a[i*3], b[2], fmaf(a[i*3+1], b[5], a[i*3+2] * b[8]));
    }
}

__global__ __launch_bounds__(THREADS, 4) void fused_kernel(
    const float* __restrict__ x, const void* __restrict__ yraw,
    const float* __restrict__ W, const float* __restrict__ bias,
    const float* __restrict__ trans, const float* __restrict__ start_t,
    const float* __restrict__ stop_t, float* __restrict__ out,
    int nrows, int out_size)
{
    __shared__ float4 ws[3 * F4_PER_ROW];   // 9 KB
    __shared__ float bs[3];
    __shared__ float feats_sm[128 * 3];     // this block's 128 rows (1.5 KB)
    __shared__ float tr_sm[9], etr_sm[9], st_sm[3], sp_sm[3];
    __shared__ float wm[4][9], wls[4], wgold[4];
    __shared__ int s_flag;

    int tid  = threadIdx.x;
    int lane = tid & 31;
    int w    = tid >> 5;

    for (int i = tid; i < 3 * F4_PER_ROW; i += THREADS)
        ws[i] = reinterpret_cast<const float4*>(W)[i];
    if (tid < 9) { float t = trans[tid]; tr_sm[tid] = t; etr_sm[tid] = __expf(t); }
    if (tid < 3) { bs[tid] = bias[tid]; st_sm[tid] = start_t[tid]; sp_sm[tid] = stop_t[tid]; }
    __syncthreads();

    // ---------------- pred: 128 rows (R4-proven inner loop, 16 rows/warp) ----------------
    int gw = blockIdx.x * 8 + w;
    #pragma unroll
    for (int q = 0; q < QPW; q++) {
        int row0 = gw * (QPW * RQ) + q * RQ;
        if (row0 >= nrows) break;
        const float4* xr = reinterpret_cast<const float4*>(x)
                           + (size_t)row0 * F4_PER_ROW + lane;

        float a[RQ][3];
        #pragma unroll
        for (int r = 0; r < RQ; r++) { a[r][0] = 0.f; a[r][1] = 0.f; a[r][2] = 0.f; }

        #pragma unroll
        for (int i = 0; i < CHUNKS; i++) {
            float4 xv[RQ];
            #pragma unroll
            for (int r = 0; r < RQ; r++)
                xv[r] = __ldcs(&xr[(size_t)r * F4_PER_ROW + i * 32]);
            float4 w0 = ws[i * 32 + lane];
            float4 w1 = ws[192 + i * 32 + lane];
            float4 w2 = ws[384 + i * 32 + lane];
            #pragma unroll
            for (int r = 0; r < RQ; r++) {
                float4 t = xv[r];
                a[r][0] = fmaf(t.x, w0.x, fmaf(t.y, w0.y, fmaf(t.z, w0.z, fmaf(t.w, w0.w, a[r][0]))));
                a[r][1] = fmaf(t.x, w1.x, fmaf(t.y, w1.y, fmaf(t.z, w1.z, fmaf(t.w, w1.w, a[r][1]))));
                a[r][2] = fmaf(t.x, w2.x, fmaf(t.y, w2.y, fmaf(t.z, w2.z, fmaf(t.w, w2.w, a[r][2]))));
            }
        }

        #pragma unroll
        for (int off = 16; off; off >>= 1) {
            #pragma unroll
            for (int r = 0; r < RQ; r++) {
                a[r][0] += __shfl_xor_sync(FULLM, a[r][0], off);
                a[r][1] += __shfl_xor_sync(FULLM, a[r][1], off);
                a[r][2] += __shfl_xor_sync(FULLM, a[r][2], off);
            }
        }
        if (lane < RQ) {
            float v0 = a[lane][0] + bs[0];
            float v1 = a[lane][1] + bs[1];
            float v2 = a[lane][2] + bs[2];
            float* o = out + (size_t)(row0 + lane) * 3;
            o[0] = v0; o[1] = v1; o[2] = v2;
            int tl = w * 16 + q * 4 + lane;        // local timestep 0..127
            feats_sm[tl * 3 + 0] = v0;
            feats_sm[tl * 3 + 1] = v1;
            feats_sm[tl * 3 + 2] = v2;
        }
    }
    __syncthreads();

    // ---------------- per-block CRF partial (overlaps other blocks' memory phase) ----------------
    int b       = blockIdx.x >> 2;           // 4 blocks per batch
    int tb_base = (blockIdx.x & 3) * 128;    // first timestep in batch

    if (w < 4) {
        // warps 0-3: chain product of 32 leaves each (1 timestep per lane)
        int tl = w * 32 + lane;
        int tb = tb_base + tl;
        float f0 = feats_sm[tl*3], f1 = feats_sm[tl*3+1], f2 = feats_sm[tl*3+2];
        if (tb == 0) { f0 += st_sm[0]; f1 += st_sm[1]; f2 += st_sm[2]; }
        float c  = fmaxf(f0, fmaxf(f1, f2));
        float e0 = __expf(f0 - c), e1 = __expf(f1 - c), e2 = __expf(f2 - c);
        float a[9]; float ls = c;
        if (tb == 0) {                        // rank-1 a0 leaf
            a[0]=e0; a[1]=e1; a[2]=e2; a[3]=e0; a[4]=e1; a[5]=e2; a[6]=e0; a[7]=e1; a[8]=e2;
        } else {
            #pragma unroll
            for (int i = 0; i < 3; i++) {
                a[i*3+0] = etr_sm[i*3+0] * e0;
                a[i*3+1] = etr_sm[i*3+1] * e1;
                a[i*3+2] = etr_sm[i*3+2] * e2;
            }
        }
        // ordered shuffle tree within warp
        #pragma unroll
        for (int off = 1; off < 32; off <<= 1) {
            float bm[9];
            #pragma unroll
            for (int e = 0; e < 9; e++) bm[e] = __shfl_down_sync(FULLM, a[e], off);
            float lsb = __shfl_down_sync(FULLM, ls, off);
            if ((lane & (2 * off - 1)) == 0) {
                float n[9];
                mm3(a, bm, n);
                #pragma unroll
                for (int e = 0; e < 9; e++) a[e] = n[e];
                ls += lsb;
                renorm9(a, ls);
            }
        }
        if (lane == 0) {
            #pragma unroll
            for (int e = 0; e < 9; e++) wm[w][e] = a[e];
            wls[w] = ls;
        }
    } else {
        // warps 4-7: gold-path partial (1 timestep per lane)
        int tl = (w - 4) * 32 + lane;
        int tb = tb_base + tl;
        // y dtype sniff (values 0..2; LE int64 -> odd 32-bit words zero)
        const int* yw = (const int*)yraw;
        int oddw = (lane < 16) ? yw[2 * lane + 1] : 0;
        int stride = (__ballot_sync(FULLM, oddw != 0) == 0u) ? 2 : 1;
        const int* yb = yw + (size_t)b * S_LEN * stride;

        int tg = yb[tb * stride];
        float g = feats_sm[tl * 3 + tg];
        if (tb > 0) { int tp = yb[(tb - 1) * stride]; g += tr_sm[tp * 3 + tg]; }
        else         g += st_sm[tg];
        if (tb == S_LEN - 1) g += sp_sm[tg];
        #pragma unroll
        for (int off = 16; off; off >>= 1) g += __shfl_xor_sync(FULLM, g, off);
        if (lane == 0) wgold[w - 4] = g;
    }
    __syncthreads();

    if (tid == 0) {
        // combine the 4 warp chain-products in order
        float p[9], n[9];
        #pragma unroll
        for (int e = 0; e < 9; e++) p[e] = wm[0][e];
        float ls = wls[0];
        #pragma unroll
        for (int j = 1; j < 4; j++) {
            mm3(p, wm[j], n);
            #pragma unroll
            for (int e = 0; e < 9; e++) p[e] = n[e];
            ls += wls[j];
            renorm9(p, ls);
        }
        #pragma unroll
        for (int e = 0; e < 9; e++) g_sm_[blockIdx.x][e] = p[e];
        g_sls[blockIdx.x] = ls;
        g_sg[blockIdx.x]  = wgold[0] + wgold[1] + wgold[2] + wgold[3];
        __threadfence();
        s_flag = (atomicAdd(&g_cnt[b], 1) == 3);
    }
    __syncthreads();
    if (!s_flag) return;

    // ---------------- batch combine: ordered product of 4 block partials ----------------
    if (tid == 0) {
        __threadfence();                     // acquire other producers' scratch
        int base = b * 4;
        float p[9], n[9], q9[9];
        #pragma unroll
        for (int e = 0; e < 9; e++) p[e] = __ldcg(&g_sm_[base][e]);
        float ls   = __ldcg(&g_sls[base]);
        float gold = __ldcg(&g_sg[base]);
        #pragma unroll
        for (int j = 1; j < 4; j++) {
            #pragma unroll
            for (int e = 0; e < 9; e++) q9[e] = __ldcg(&g_sm_[base + j][e]);
            mm3(p, q9, n);
            #pragma unroll
            for (int e = 0; e < 9; e++) p[e] = n[e];
            ls += __ldcg(&g_sls[base + j]);
            renorm9(p, ls);
            gold += __ldcg(&g_sg[base + j]);
        }
        float z = p[0] * __expf(sp_sm[0]) + p[1] * __expf(sp_sm[1]) + p[2] * __expf(sp_sm[2]);
        g_part[b] = gold - (ls + __logf(z));
        g_cnt[b] = 0;                        // self-reset for next graph replay
        __threadfence();
        s_flag = ((int)atomicAdd(&g_done, 1) == B_SZ - 1);
    }
    __syncthreads();

    // ---------------- finalize: 128th batch-completer reduces all partials ----------------
    if (s_flag && w == 0) {
        __threadfence();
        float s = __ldcg(&g_part[lane])      + __ldcg(&g_part[lane + 32])
                + __ldcg(&g_part[lane + 64]) + __ldcg(&g_part[lane + 96]);
        #pragma unroll
        for (int off = 16; off; off >>= 1) s += __shfl_xor_sync(FULLM, s, off);
        if (lane == 0) {
            out[out_size - 1] = -s / (float)B_SZ;
            g_done = 0;                      // self-reset for next graph replay
        }
    }
}

// ---------------- launch ----------------
extern "C" void kernel_launch(void* const* d_in, const int* in_sizes, int n_in,
                              void* d_out, int out_size)
{
    const float* x     = (const float*)d_in[0];
    const void*  y     = d_in[1];
    const float* W     = (const float*)d_in[2];
    const float* bias  = (const float*)d_in[3];
    const float* trans = (const float*)d_in[4];
    const float* st    = (const float*)d_in[5];
    const float* sp    = (const float*)d_in[6];
    float* out = (float*)d_out;

    int nrows = in_sizes[0] / H_DIM;    // 65536

    fused_kernel<<<BLOCKS, THREADS>>>(x, y, W, bias, trans, st, sp,
                                      out, nrows, out_size);
}